// round 1
// baseline (speedup 1.0000x reference)
#include <cuda_runtime.h>
#include <cuda_bf16.h>
#include <cstdint>

// u_quant_weight_linear: per-out-channel uniform symmetric fake quantization.
// out[o,i] = clip(rint(w[o,i]/s), -qmax, qmax) * s
//   s    = max(alh[o], 1e-5)
//   b    = rint(clip(|bit[o]|, 1, 6))
//   qmax = max(2^(b-1) - 1, 1)
//
// Shapes: weight [4096, 11008] f32, alh [4096,1] f32, bit [4096,1] f32.
// 11008 / 4 = 2752 float4 per row. Purely HBM-bound (360 MB traffic).

#define OUT_CH   4096
#define IN_FEAT  11008
#define VEC_PER_ROW (IN_FEAT / 4)   // 2752

__global__ __launch_bounds__(256)
void fake_quant_kernel(const float4* __restrict__ w,
                       const float*  __restrict__ alh,
                       const float*  __restrict__ bit,
                       float4* __restrict__ out)
{
    const int row = blockIdx.y;
    const int col = blockIdx.x * blockDim.x + threadIdx.x;  // float4 column
    if (col >= VEC_PER_ROW) return;

    // Per-row scalars: broadcast load, L2/L1 resident after first touch.
    const float s    = fmaxf(alh[row], 1e-5f);
    const float b    = rintf(fminf(fmaxf(fabsf(bit[row]), 1.0f), 6.0f));
    const float qmax = fmaxf(exp2f(b - 1.0f) - 1.0f, 1.0f);
    const float qmin = -qmax;

    const size_t idx = (size_t)row * VEC_PER_ROW + col;
    float4 v = w[idx];

    // True IEEE divide so rint() decisions match the reference exactly.
    v.x = fminf(fmaxf(rintf(v.x / s), qmin), qmax) * s;
    v.y = fminf(fmaxf(rintf(v.y / s), qmin), qmax) * s;
    v.z = fminf(fmaxf(rintf(v.z / s), qmin), qmax) * s;
    v.w = fminf(fmaxf(rintf(v.w / s), qmin), qmax) * s;

    out[idx] = v;
}

extern "C" void kernel_launch(void* const* d_in, const int* in_sizes, int n_in,
                              void* d_out, int out_size)
{
    const float4* w   = (const float4*)d_in[0];  // weight [4096, 11008]
    const float*  alh = (const float*)d_in[1];   // [4096, 1]
    const float*  bit = (const float*)d_in[2];   // [4096, 1]
    float4* out = (float4*)d_out;

    dim3 block(256);
    dim3 grid((VEC_PER_ROW + 255) / 256, OUT_CH);  // (11, 4096)
    fake_quant_kernel<<<grid, block>>>(w, alh, bit, out);
}

// round 2
// speedup vs baseline: 1.0556x; 1.0556x over previous
#include <cuda_runtime.h>
#include <cuda_bf16.h>
#include <cstdint>

// u_quant_weight_linear: per-out-channel uniform symmetric fake quantization.
// out[o,i] = clip(rint(w[o,i]/s), -qmax, qmax) * s
//   s    = max(alh[o], 1e-5)
//   b    = rint(clip(|bit[o]|, 1, 6))
//   qmax = max(2^(b-1) - 1, 1)
//
// weight [4096, 11008] f32. 2752 float4 per row.
// One block per row; 256 threads; 11 front-batched coalesced float4 loads
// per thread (10 full strides + predicated tail of 192) -> MLP_p1 = 11.

#define OUT_CH      4096
#define IN_FEAT     11008
#define VEC_PER_ROW (IN_FEAT / 4)   // 2752
#define FULL_ITERS  10              // 10*256 = 2560
#define TAIL_THREADS (VEC_PER_ROW - FULL_ITERS * 256)  // 192

__global__ __launch_bounds__(256)
void fake_quant_kernel(const float4* __restrict__ w,
                       const float*  __restrict__ alh,
                       const float*  __restrict__ bit,
                       float4* __restrict__ out)
{
    const int row = blockIdx.x;
    const int tid = threadIdx.x;

    // Per-row scalars (uniform across block; L1/L2 broadcast).
    const float s    = fmaxf(alh[row], 1e-5f);
    const float b    = rintf(fminf(fmaxf(fabsf(bit[row]), 1.0f), 6.0f));
    const float qmax = fmaxf(exp2f(b - 1.0f) - 1.0f, 1.0f);
    const float qmin = -qmax;

    const float4* __restrict__ wr = w   + (size_t)row * VEC_PER_ROW;
    float4*       __restrict__ orw = out + (size_t)row * VEC_PER_ROW;

    const bool tail = tid < TAIL_THREADS;

    // Front-batch all loads: 11 independent LDG.128 in flight per thread.
    float4 v[FULL_ITERS + 1];
    #pragma unroll
    for (int i = 0; i < FULL_ITERS; i++)
        v[i] = wr[tid + i * 256];
    v[FULL_ITERS] = tail ? wr[tid + FULL_ITERS * 256]
                         : make_float4(0.f, 0.f, 0.f, 0.f);

    // Quantize + store (compute interleaved with stores keeps reg pressure
    // at the load batch, not 2x).
    #pragma unroll
    for (int i = 0; i <= FULL_ITERS; i++) {
        float4 q = v[i];
        // True IEEE divide: rint decisions must match the reference exactly
        // (reciprocal-multiply can flip elements quantizing to 0).
        q.x = fminf(fmaxf(rintf(q.x / s), qmin), qmax) * s;
        q.y = fminf(fmaxf(rintf(q.y / s), qmin), qmax) * s;
        q.z = fminf(fmaxf(rintf(q.z / s), qmin), qmax) * s;
        q.w = fminf(fmaxf(rintf(q.w / s), qmin), qmax) * s;
        if (i < FULL_ITERS)
            orw[tid + i * 256] = q;
        else if (tail)
            orw[tid + FULL_ITERS * 256] = q;
    }
}

extern "C" void kernel_launch(void* const* d_in, const int* in_sizes, int n_in,
                              void* d_out, int out_size)
{
    const float4* w   = (const float4*)d_in[0];  // weight [4096, 11008]
    const float*  alh = (const float*)d_in[1];   // [4096, 1]
    const float*  bit = (const float*)d_in[2];   // [4096, 1]
    float4* out = (float4*)d_out;

    fake_quant_kernel<<<OUT_CH, 256>>>(w, alh, bit, out);
}

// round 3
// speedup vs baseline: 1.0661x; 1.0099x over previous
#include <cuda_runtime.h>
#include <cuda_bf16.h>
#include <cstdint>

// u_quant_weight_linear: per-out-channel uniform symmetric fake quantization.
// out[o,i] = clip(rint(w[o,i]/s), -qmax, qmax) * s
//   s    = max(alh[o], 1e-5)
//   b    = rint(clip(|bit[o]|, 1, 6))
//   qmax = max(2^(b-1) - 1, 1)
//
// weight [4096, 11008] f32 = 2752 float4/row.
// R3: one block per row, 512 threads, 6 front-batched float4 (5 full + tail)
// -> 24 data regs; __launch_bounds__(512,3) caps regs for 75% occupancy.
// Streaming hints (__ldcs/__stcs): 360MB pure stream shouldn't thrash L2.

#define OUT_CH       4096
#define IN_FEAT      11008
#define VEC_PER_ROW  (IN_FEAT / 4)            // 2752
#define NTHREADS     512
#define FULL_ITERS   5                         // 5*512 = 2560
#define TAIL_THREADS (VEC_PER_ROW - FULL_ITERS * NTHREADS)  // 192

__global__ __launch_bounds__(NTHREADS, 3)
void fake_quant_kernel(const float4* __restrict__ w,
                       const float*  __restrict__ alh,
                       const float*  __restrict__ bit,
                       float4* __restrict__ out)
{
    const int row = blockIdx.x;
    const int tid = threadIdx.x;

    // Per-row scalars (uniform across block).
    const float s    = fmaxf(alh[row], 1e-5f);
    const float b    = rintf(fminf(fmaxf(fabsf(bit[row]), 1.0f), 6.0f));
    const float qmax = fmaxf(exp2f(b - 1.0f) - 1.0f, 1.0f);
    const float qmin = -qmax;

    const float4* __restrict__ wr  = w   + (size_t)row * VEC_PER_ROW;
    float4*       __restrict__ orw = out + (size_t)row * VEC_PER_ROW;

    const bool tail = tid < TAIL_THREADS;

    // Front-batch all 6 loads (streaming: evict-first in L1/L2).
    float4 v[FULL_ITERS + 1];
    #pragma unroll
    for (int i = 0; i < FULL_ITERS; i++)
        v[i] = __ldcs(&wr[tid + i * NTHREADS]);
    v[FULL_ITERS] = tail ? __ldcs(&wr[tid + FULL_ITERS * NTHREADS])
                         : make_float4(0.f, 0.f, 0.f, 0.f);

    #pragma unroll
    for (int i = 0; i <= FULL_ITERS; i++) {
        float4 q = v[i];
        // True IEEE divide: rint decisions must match the reference exactly.
        q.x = fminf(fmaxf(rintf(q.x / s), qmin), qmax) * s;
        q.y = fminf(fmaxf(rintf(q.y / s), qmin), qmax) * s;
        q.z = fminf(fmaxf(rintf(q.z / s), qmin), qmax) * s;
        q.w = fminf(fmaxf(rintf(q.w / s), qmin), qmax) * s;
        if (i < FULL_ITERS)
            __stcs(&orw[tid + i * NTHREADS], q);
        else if (tail)
            __stcs(&orw[tid + FULL_ITERS * NTHREADS], q);
    }
}

extern "C" void kernel_launch(void* const* d_in, const int* in_sizes, int n_in,
                              void* d_out, int out_size)
{
    const float4* w   = (const float4*)d_in[0];  // weight [4096, 11008]
    const float*  alh = (const float*)d_in[1];   // [4096, 1]
    const float*  bit = (const float*)d_in[2];   // [4096, 1]
    float4* out = (float4*)d_out;

    fake_quant_kernel<<<OUT_CH, NTHREADS>>>(w, alh, bit, out);
}